// round 1
// baseline (speedup 1.0000x reference)
#include <cuda_runtime.h>

// ---------------------------------------------------------------------------
// MultiHeadAttention graph block, GB300 fp32 (f32x2 packed FMA) implementation
// B=2, N=256, NODE_DIM=256, EDGE_DIM=64, H=8, D=32
// Inputs: 0 nodes[2,256,256] 1 edges[2,256,256,64] 2 W_qkv[256,768] 3 b_qkv[768]
//         4 W_ss[64,512] 5 b_ss[512] 6 W_nodes[256,256] 7 b_nodes[256]
//         8 W_edges[256,64] 9 b_edges[64]
// Output: new_nodes [2,256,256] (131072 f32) then new_edges_out [2,256,256,64]
// ---------------------------------------------------------------------------

typedef unsigned long long U64;

__device__ __forceinline__ U64 pk2(float lo, float hi) {
    U64 r; asm("mov.b64 %0,{%1,%2};" : "=l"(r) : "f"(lo), "f"(hi)); return r;
}
__device__ __forceinline__ void fma2(U64& d, U64 a, U64 b) {
    asm("fma.rn.f32x2 %0,%1,%2,%0;" : "+l"(d) : "l"(a), "l"(b));
}
__device__ __forceinline__ float2 up2(U64 v) {
    float2 r; asm("mov.b64 {%0,%1},%2;" : "=f"(r.x), "=f"(r.y) : "l"(v)); return r;
}

// Scratch (device globals: no allocation allowed)
__device__ float g_QKV[512 * 768];        // qkv rows: [b*256+n][768], q|k|v at col 0/256/512
__device__ float g_att[2 * 8 * 256 * 256]; // logits -> attention in place, layout [b][h][k][q]
__device__ float g_wt[512 * 256];          // weighted [b*256+q][256]

// ---------------------------------------------------------------------------
// Generic small GEMM with bias: C[M,N] = A[M,K] @ B[K,N] + bias  (M,N mult 64, K mult 16)
// ---------------------------------------------------------------------------
__global__ void __launch_bounds__(256) gemm_bias_kernel(
    const float* __restrict__ A, const float* __restrict__ B,
    const float* __restrict__ bias, float* __restrict__ C,
    int M, int K, int N)
{
    __shared__ float sA[16][65];   // [kk][m]
    __shared__ float sB[16][64];   // [kk][n]
    const int nb = N >> 6;
    const int m0 = (blockIdx.x / nb) << 6;
    const int n0 = (blockIdx.x % nb) << 6;
    const int tm = threadIdx.x >> 4, tn = threadIdx.x & 15;

    float acc[4][4] = {};
    for (int kc = 0; kc < K; kc += 16) {
        {
            const int t = threadIdx.x;
            const int m = t >> 2, k4 = (t & 3) << 2;
            float4 a = *(const float4*)&A[(m0 + m) * K + kc + k4];
            sA[k4 + 0][m] = a.x; sA[k4 + 1][m] = a.y;
            sA[k4 + 2][m] = a.z; sA[k4 + 3][m] = a.w;
            const int kk = t >> 4, n4 = (t & 15) << 2;
            *(float4*)&sB[kk][n4] = *(const float4*)&B[(kc + kk) * N + n0 + n4];
        }
        __syncthreads();
#pragma unroll
        for (int kk = 0; kk < 16; kk++) {
            float a0 = sA[kk][tm * 4 + 0], a1 = sA[kk][tm * 4 + 1];
            float a2 = sA[kk][tm * 4 + 2], a3 = sA[kk][tm * 4 + 3];
            float4 b4 = *(float4*)&sB[kk][tn * 4];
            acc[0][0] += a0 * b4.x; acc[0][1] += a0 * b4.y; acc[0][2] += a0 * b4.z; acc[0][3] += a0 * b4.w;
            acc[1][0] += a1 * b4.x; acc[1][1] += a1 * b4.y; acc[1][2] += a1 * b4.z; acc[1][3] += a1 * b4.w;
            acc[2][0] += a2 * b4.x; acc[2][1] += a2 * b4.y; acc[2][2] += a2 * b4.z; acc[2][3] += a2 * b4.w;
            acc[3][0] += a3 * b4.x; acc[3][1] += a3 * b4.y; acc[3][2] += a3 * b4.z; acc[3][3] += a3 * b4.w;
        }
        __syncthreads();
    }
    float4 bb = *(const float4*)&bias[n0 + tn * 4];
#pragma unroll
    for (int i = 0; i < 4; i++) {
        float4 o = make_float4(acc[i][0] + bb.x, acc[i][1] + bb.y,
                               acc[i][2] + bb.z, acc[i][3] + bb.w);
        *(float4*)&C[(m0 + tm * 4 + i) * N + n0 + tn * 4] = o;
    }
}

// ---------------------------------------------------------------------------
// Main fused edge kernel. Block = (b, q, 32-k tile). 256 threads.
// Phase A: ss GEMM [32 pairs][512] = edges_tile[32,64] @ W_ss[64,512]  (f32x2)
// Phase B: ne = q*k*(1+scale)+shift ; logits ; lrelu(ne) -> smem
// Phase C: out = lrelu(ne)[32,256] @ W_edges[256,64] + b_edges       (f32x2)
// ---------------------------------------------------------------------------
__global__ void __launch_bounds__(256, 2) main_edge_kernel(
    const float* __restrict__ edges, const float* __restrict__ W_ss,
    const float* __restrict__ b_ss, const float* __restrict__ W_edges,
    const float* __restrict__ b_edges, float* __restrict__ out_edges,
    float* __restrict__ logits)
{
    extern __shared__ float sm[];
    float* sA   = sm;                 // edges^T [64 kk][33 pairs]      (2112 f)
    float* sQ   = sm + 2112;          // q row (256 f)
    float* sBNE = sm + 2112 + 256;    // W_ss stage [16][512] then NE [32][264] (8448 f)

    const int bid = blockIdx.x;
    const int b  = bid >> 11;
    const int q  = (bid >> 3) & 255;
    const int k0 = (bid & 7) << 5;
    const int tid = threadIdx.x;
    const int tc = tid & 31, tp = tid >> 5;
    const int cb = tc << 3;            // c base (8 contiguous c per thread)

    // load edges tile transposed + q row
    {
        const float* ep = edges + (((size_t)(b << 8) + q) * 256 + k0) * 64;
#pragma unroll
        for (int r = 0; r < 2; r++) {
            int idx4 = tid + r * 256;           // 0..511 float4s
            float4 v = *(const float4*)(ep + idx4 * 4);
            int pair = idx4 >> 4;
            int kk = (idx4 & 15) << 2;
            sA[(kk + 0) * 33 + pair] = v.x; sA[(kk + 1) * 33 + pair] = v.y;
            sA[(kk + 2) * 33 + pair] = v.z; sA[(kk + 3) * 33 + pair] = v.w;
        }
        if (tid < 64)
            *(float4*)&sQ[tid * 4] = *(const float4*)&g_QKV[((b << 8) + q) * 768 + tid * 4];
    }

    // -------- Phase A: ss GEMM, packed accumulators --------
    U64 aS[4][4] = {}, aC[4][4] = {};   // [pair][cpack] shift / scale
    for (int s = 0; s < 4; s++) {
        __syncthreads();
#pragma unroll
        for (int r = 0; r < 8; r++) {
            int idx4 = tid + r * 256;                 // 2048 float4s = 16x512
            int row = idx4 >> 7, col = (idx4 & 127) << 2;
            *(float4*)&sBNE[row * 512 + col] =
                *(const float4*)&W_ss[(s * 16 + row) * 512 + col];
        }
        __syncthreads();
#pragma unroll
        for (int kk = 0; kk < 16; kk++) {
            const float* ar = &sA[(s * 16 + kk) * 33 + (tp << 2)];
            float a0 = ar[0], a1 = ar[1], a2 = ar[2], a3 = ar[3];
            const float* br = &sBNE[kk * 512];
            float4 s0 = *(const float4*)(br + cb),       s1 = *(const float4*)(br + cb + 4);
            float4 c0 = *(const float4*)(br + 256 + cb), c1 = *(const float4*)(br + 256 + cb + 4);
            U64 bS[4] = { pk2(s0.x, s0.y), pk2(s0.z, s0.w), pk2(s1.x, s1.y), pk2(s1.z, s1.w) };
            U64 bC[4] = { pk2(c0.x, c0.y), pk2(c0.z, c0.w), pk2(c1.x, c1.y), pk2(c1.z, c1.w) };
            U64 A0 = pk2(a0, a0), A1 = pk2(a1, a1), A2 = pk2(a2, a2), A3 = pk2(a3, a3);
#pragma unroll
            for (int j = 0; j < 4; j++) {
                fma2(aS[0][j], A0, bS[j]); fma2(aC[0][j], A0, bC[j]);
                fma2(aS[1][j], A1, bS[j]); fma2(aC[1][j], A1, bC[j]);
                fma2(aS[2][j], A2, bS[j]); fma2(aC[2][j], A2, bC[j]);
                fma2(aS[3][j], A3, bS[j]); fma2(aC[3][j], A3, bC[j]);
            }
        }
    }
    __syncthreads();   // all reads of W_ss stage done before NE overwrites it

    // -------- Phase B: ne, logits, lrelu -> smem --------
    float bsh[8], bsc[8], qv[8];
    *(float4*)&bsh[0] = *(const float4*)&b_ss[cb];
    *(float4*)&bsh[4] = *(const float4*)&b_ss[cb + 4];
    *(float4*)&bsc[0] = *(const float4*)&b_ss[256 + cb];
    *(float4*)&bsc[4] = *(const float4*)&b_ss[256 + cb + 4];
    *(float4*)&qv[0] = *(float4*)&sQ[cb];
    *(float4*)&qv[4] = *(float4*)&sQ[cb + 4];

#pragma unroll
    for (int p = 0; p < 4; p++) {
        const int pi = (tp << 2) + p;
        const int k = k0 + pi;
        const float* kr = &g_QKV[((b << 8) + k) * 768 + 256 + cb];
        float kv[8];
        *(float4*)&kv[0] = *(const float4*)kr;
        *(float4*)&kv[4] = *(const float4*)(kr + 4);
        float lg = 0.f;
        float ne[8];
#pragma unroll
        for (int jj = 0; jj < 4; jj++) {
            float2 sh2 = up2(aS[p][jj]);
            float2 sc2 = up2(aC[p][jj]);
            float sh0 = sh2.x + bsh[2 * jj],     sh1 = sh2.y + bsh[2 * jj + 1];
            float sc0 = sc2.x + bsc[2 * jj],     sc1 = sc2.y + bsc[2 * jj + 1];
            float qk0 = qv[2 * jj] * kv[2 * jj];
            float qk1 = qv[2 * jj + 1] * kv[2 * jj + 1];
            float n0 = fmaf(qk0, sc0, qk0) + sh0;
            float n1 = fmaf(qk1, sc1, qk1) + sh1;
            lg += n0 + n1;
            ne[2 * jj]     = n0 > 0.f ? n0 : 0.1f * n0;
            ne[2 * jj + 1] = n1 > 0.f ? n1 : 0.1f * n1;
        }
        float* nr = &sBNE[pi * 264 + cb];
        *(float4*)nr       = make_float4(ne[0], ne[1], ne[2], ne[3]);
        *(float4*)(nr + 4) = make_float4(ne[4], ne[5], ne[6], ne[7]);
        lg += __shfl_xor_sync(0xffffffffu, lg, 1);
        lg += __shfl_xor_sync(0xffffffffu, lg, 2);
        if ((tc & 3) == 0) {
            int h = tc >> 2;
            logits[(((b << 3) + h) * 256 + k) * 256 + q] = lg * 0.17677669529663687f;
        }
    }
    __syncthreads();   // NE fully written

    // -------- Phase C: edge output GEMM --------
    const int tp2 = tid >> 4, te = tid & 15;   // pairs 2*tp2, e = te*4
    U64 o[2][2] = {};
    float* sW = sA;   // reuse edges-tile region (2048 <= 2112 floats)
    for (int s2 = 0; s2 < 8; s2++) {
#pragma unroll
        for (int r = 0; r < 2; r++) {
            int idx4 = tid + r * 256;            // 512 float4s = 32x64
            int row = idx4 >> 4, col = (idx4 & 15) << 2;
            *(float4*)&sW[row * 64 + col] =
                *(const float4*)&W_edges[(s2 * 32 + row) * 64 + col];
        }
        __syncthreads();
#pragma unroll
        for (int kk = 0; kk < 32; kk++) {
            int k2 = s2 * 32 + kk;
            float n0 = sBNE[(tp2 * 2) * 264 + k2];
            float n1 = sBNE[(tp2 * 2 + 1) * 264 + k2];
            float4 w = *(const float4*)&sW[kk * 64 + te * 4];
            U64 w01 = pk2(w.x, w.y), w23 = pk2(w.z, w.w);
            U64 N0 = pk2(n0, n0), N1 = pk2(n1, n1);
            fma2(o[0][0], N0, w01); fma2(o[0][1], N0, w23);
            fma2(o[1][0], N1, w01); fma2(o[1][1], N1, w23);
        }
        __syncthreads();
    }
    float4 be = *(const float4*)&b_edges[te * 4];
#pragma unroll
    for (int p = 0; p < 2; p++) {
        float2 x0 = up2(o[p][0]), x1 = up2(o[p][1]);
        float4 res = make_float4(x0.x + be.x, x0.y + be.y, x1.x + be.z, x1.y + be.w);
        int k = k0 + tp2 * 2 + p;
        *(float4*)&out_edges[(((size_t)(b << 8) + q) * 256 + k) * 64 + te * 4] = res;
    }
}

// ---------------------------------------------------------------------------
// Softmax over q for each (b,h,k). Rows of g_att are contiguous in q. In place.
// ---------------------------------------------------------------------------
__global__ void __launch_bounds__(256) softmax_q_kernel(float* __restrict__ lg)
{
    const int row = blockIdx.x * 8 + (threadIdx.x >> 5);
    const int lane = threadIdx.x & 31;
    float* p = lg + (size_t)row * 256;
    float4 v0 = *(float4*)&p[lane * 8];
    float4 v1 = *(float4*)&p[lane * 8 + 4];
    float v[8] = { v0.x, v0.y, v0.z, v0.w, v1.x, v1.y, v1.z, v1.w };
    float m = v[0];
#pragma unroll
    for (int i = 1; i < 8; i++) m = fmaxf(m, v[i]);
#pragma unroll
    for (int off = 16; off > 0; off >>= 1) m = fmaxf(m, __shfl_xor_sync(0xffffffffu, m, off));
    float s = 0.f;
#pragma unroll
    for (int i = 0; i < 8; i++) { v[i] = __expf(v[i] - m); s += v[i]; }
#pragma unroll
    for (int off = 16; off > 0; off >>= 1) s += __shfl_xor_sync(0xffffffffu, s, off);
    float inv = 1.f / s;
    *(float4*)&p[lane * 8]     = make_float4(v[0] * inv, v[1] * inv, v[2] * inv, v[3] * inv);
    *(float4*)&p[lane * 8 + 4] = make_float4(v[4] * inv, v[5] * inv, v[6] * inv, v[7] * inv);
}

// ---------------------------------------------------------------------------
// weighted[b,q,h*32+d] = sum_k att[b,h,k,q] * V[b,k,h*32+d]
// grid (qc=4, h=8, b=2), 256 threads = 64 q x (4 groups of 8 d)
// ---------------------------------------------------------------------------
__global__ void __launch_bounds__(256) attnv_kernel(const float* __restrict__ att,
                                                    float* __restrict__ wt)
{
    __shared__ float sv[32][32];
    const int b = blockIdx.z, h = blockIdx.y, qc = blockIdx.x;
    const int dg = threadIdx.x >> 6, qq = threadIdx.x & 63;
    const int q = qc * 64 + qq;
    float acc[8] = {};
    for (int kc = 0; kc < 8; kc++) {
        __syncthreads();
        {
            int row = threadIdx.x >> 3, c4 = (threadIdx.x & 7) << 2;
            *(float4*)&sv[row][c4] =
                *(const float4*)&g_QKV[((b << 8) + kc * 32 + row) * 768 + 512 + h * 32 + c4];
        }
        __syncthreads();
        const float* ap = att + (((size_t)((b << 3) + h)) * 256 + kc * 32) * 256 + q;
#pragma unroll
        for (int kk = 0; kk < 32; kk++) {
            float a = ap[(size_t)kk * 256];
            float4 u0 = *(float4*)&sv[kk][dg * 8];
            float4 u1 = *(float4*)&sv[kk][dg * 8 + 4];
            acc[0] += a * u0.x; acc[1] += a * u0.y; acc[2] += a * u0.z; acc[3] += a * u0.w;
            acc[4] += a * u1.x; acc[5] += a * u1.y; acc[6] += a * u1.z; acc[7] += a * u1.w;
        }
    }
    float* wp = &wt[((b << 8) + q) * 256 + h * 32 + dg * 8];
    *(float4*)wp       = make_float4(acc[0], acc[1], acc[2], acc[3]);
    *(float4*)(wp + 4) = make_float4(acc[4], acc[5], acc[6], acc[7]);
}

// ---------------------------------------------------------------------------
extern "C" void kernel_launch(void* const* d_in, const int* in_sizes, int n_in,
                              void* d_out, int out_size)
{
    const float* nodes   = (const float*)d_in[0];
    const float* edges   = (const float*)d_in[1];
    const float* W_qkv   = (const float*)d_in[2];
    const float* b_qkv   = (const float*)d_in[3];
    const float* W_ss    = (const float*)d_in[4];
    const float* b_ss    = (const float*)d_in[5];
    const float* W_nodes = (const float*)d_in[6];
    const float* b_nodes = (const float*)d_in[7];
    const float* W_edges = (const float*)d_in[8];
    const float* b_edges = (const float*)d_in[9];

    float* out_nodes = (float*)d_out;
    float* out_edges = out_nodes + 512 * 256;

    float *qkvp = nullptr, *attp = nullptr, *wtp = nullptr;
    cudaGetSymbolAddress((void**)&qkvp, g_QKV);
    cudaGetSymbolAddress((void**)&attp, g_att);
    cudaGetSymbolAddress((void**)&wtp, g_wt);

    // 1) qkv = nodes @ W_qkv + b_qkv : [512,768], K=256
    gemm_bias_kernel<<<(512 / 64) * (768 / 64), 256>>>(nodes, W_qkv, b_qkv, qkvp, 512, 256, 768);

    // 2) fused edge pipeline (ss GEMM + ne + logits + lrelu + edge-out GEMM)
    const int smem = (2112 + 256 + 8448) * sizeof(float);  // 43264 B
    main_edge_kernel<<<2 * 256 * 8, 256, smem>>>(edges, W_ss, b_ss, W_edges, b_edges,
                                                 out_edges, attp);

    // 3) softmax over q for each (b,h,k) — 4096 rows, 8 rows/block
    softmax_q_kernel<<<512, 256>>>(attp);

    // 4) weighted = einsum('bhqk,bhkd->bqhd', att, v)
    attnv_kernel<<<dim3(4, 8, 2), 256>>>(attp, wtp);

    // 5) new_nodes = weighted @ W_nodes + b_nodes : [512,256], K=256
    gemm_bias_kernel<<<(512 / 64) * (256 / 64), 256>>>(wtp, W_nodes, b_nodes, out_nodes,
                                                       512, 256, 256);
}